// round 16
// baseline (speedup 1.0000x reference)
#include <cuda_runtime.h>
#include <stdint.h>

// ---------------------------------------------------------------------------
// PillarMotionNet voxelization, v6: no acc.w repack. Rank derived in feat
// from {mask, wordOffset} pairs (800 KB, L2-hot); k_rank only emits unq.
//   points: (N, 6) float32 rows [batch, x, y, z, intensity, time]
//   out   : [features (N*9) | unq (N*4) | unq_inv (N) | grid (3)] float32
// ---------------------------------------------------------------------------

#define GX 400
#define GY 400
#define NTIME 5
#define NBATCH 4
#define NKEYS (NBATCH * GX * GY * NTIME)   // 3,200,000
#define NWORDS (NKEYS / 32)                // 100,000
#define GRAN 128                           // words per scan block
#define NSB ((NWORDS + GRAN - 1) / GRAN)   // 782

// __device__ global scratch (allocation-free rule)
__device__ float4   g_acc[NKEYS];     // {sum_x, sum_y, sum_z, count} (never modified after accum)
__device__ unsigned g_mask[NWORDS];   // occupancy bitmask
__device__ int2     g_mw[NWORDS];     // {mask, exclusive word offset}
__device__ int      g_blockCnt[NSB];
__device__ int      g_total;

// ---------------------------------------------------------------------------
// 1) Zero accumulator + bitmask + total. NKEYS = 12500 * 256 exactly.
// ---------------------------------------------------------------------------
__global__ void k_init() {
    int i = blockIdx.x * 256 + threadIdx.x;
    g_acc[i] = make_float4(0.0f, 0.0f, 0.0f, 0.0f);
    if (i < NWORDS) g_mask[i] = 0u;
    if (i == 0) g_total = 0;
}

// ---------------------------------------------------------------------------
// 2) Two points per thread: 3 x float4 loads, v4 RED + bitmask OR each.
// ---------------------------------------------------------------------------
__device__ __forceinline__ void accum_one(float b_f, float x, float y, float z,
                                          float t_f) {
    int cx = (int)((x + 50.0f) * 4.0f);
    int cy = (int)((y + 50.0f) * 4.0f);
    int key = (((int)b_f * GX + cx) * GY + cy) * NTIME + (int)t_f;
    float4* addr = &g_acc[key];
    asm volatile("red.global.add.v4.f32 [%0], {%1, %2, %3, %4};"
                 :: "l"(addr), "f"(x), "f"(y), "f"(z), "f"(1.0f) : "memory");
    atomicOr(&g_mask[key >> 5], 1u << (key & 31));
}

__global__ void k_accum(const float* __restrict__ pts, int N) {
    int t = blockIdx.x * blockDim.x + threadIdx.x;
    int i0 = t * 2;
    if (i0 >= N) return;
    if (i0 + 1 < N) {
        const float4* q = (const float4*)(pts + (size_t)i0 * 6);
        float4 A = __ldg(q);       // b0 x0 y0 z0
        float4 B = __ldg(q + 1);   // i0 t0 b1 x1
        float4 C = __ldg(q + 2);   // y1 z1 i1 t1
        accum_one(A.x, A.y, A.z, A.w, B.y);
        accum_one(B.z, B.w, C.x, C.y, C.w);
    } else {
        const float* p = pts + (size_t)i0 * 6;
        accum_one(p[0], p[1], p[2], p[3], p[5]);
    }
}

// ---------------------------------------------------------------------------
// 3a) Per-scan-block (128 words) occupancy count + grand total.
// ---------------------------------------------------------------------------
__global__ void k_scan1() {
    int w = blockIdx.x * GRAN + threadIdx.x;
    int c = (w < NWORDS) ? __popc(g_mask[w]) : 0;
    #pragma unroll
    for (int o = 16; o > 0; o >>= 1) c += __shfl_down_sync(0xffffffffu, c, o);
    __shared__ int ws[4];
    int lane = threadIdx.x & 31, warp = threadIdx.x >> 5;
    if (lane == 0) ws[warp] = c;
    __syncthreads();
    if (threadIdx.x == 0) {
        int s = ws[0] + ws[1] + ws[2] + ws[3];
        g_blockCnt[blockIdx.x] = s;
        atomicAdd(&g_total, s);
    }
}

// ---------------------------------------------------------------------------
// 3b) Word offsets + lane-parallel unq emission. NO g_acc access.
//     Phase 1: block exclusive offset (sum g_blockCnt[0..bid)).
//     Phase 2: word offsets -> g_mw[w] = {mask, off}  (+ smem copy).
//     Phase 3: 8 warps sweep 128 words; lane b owns bit b; unq float4
//              stores land at consecutive ranks (coalesced).
// ---------------------------------------------------------------------------
__global__ void k_rank(float4* __restrict__ u4) {
    __shared__ int red8[8];
    __shared__ int scan4[4];
    __shared__ int s_base;
    __shared__ unsigned s_m[GRAN];
    __shared__ int s_off[GRAN];
    int tid = threadIdx.x, lane = tid & 31, warp = tid >> 5;

    // exclusive block offset
    int partial = 0;
    for (int j = tid; j < blockIdx.x; j += 256) partial += g_blockCnt[j];
    #pragma unroll
    for (int o = 16; o > 0; o >>= 1)
        partial += __shfl_down_sync(0xffffffffu, partial, o);
    if (lane == 0) red8[warp] = partial;
    __syncthreads();
    if (tid == 0) {
        int s = 0;
        #pragma unroll
        for (int k = 0; k < 8; k++) s += red8[k];
        s_base = s;
    }

    // per-word exclusive prefix (threads 0..127 own one word each)
    int w = blockIdx.x * GRAN + tid;
    unsigned m = 0u;
    int c = 0;
    if (tid < GRAN) {
        m = (w < NWORDS) ? g_mask[w] : 0u;
        c = __popc(m);
    }
    int v = c;
    #pragma unroll
    for (int o = 1; o < 32; o <<= 1) {
        int u = __shfl_up_sync(0xffffffffu, v, o);
        if (lane >= o) v += u;
    }
    if (tid < GRAN && lane == 31) scan4[warp] = v;
    __syncthreads();
    if (tid < GRAN) {
        int wb = 0;
        #pragma unroll
        for (int k = 0; k < 4; k++) wb += (k < warp) ? scan4[k] : 0;
        int off = s_base + wb + (v - c);
        s_m[tid] = m;
        s_off[tid] = off;
        if (w < NWORDS) g_mw[w] = make_int2((int)m, off);
    }
    __syncthreads();

    // lane-parallel unq emission
    int wordBase = blockIdx.x * GRAN;
    for (int j = warp; j < GRAN; j += 8) {
        unsigned mm = s_m[j];
        if (mm == 0u) continue;                 // warp-uniform
        if ((mm >> lane) & 1u) {
            int rank = s_off[j] + __popc(mm & ((1u << lane) - 1u));
            int key = (wordBase + j) * 32 + lane;
            int k2 = key;
            int tt = k2 % NTIME; k2 /= NTIME;
            int yy = k2 % GY;    k2 /= GY;
            int xx = k2 % GX;
            int bb = k2 / GX;
            u4[rank] = make_float4((float)bb, (float)tt, (float)yy, (float)xx);
        }
    }
}

// ---------------------------------------------------------------------------
// 4) Per-point features, 1 pt/thread (R8 structure): one 16B acc gather +
//    one 8B mw gather (800 KB hot), smem-staged coalesced float4 stores,
//    unq_inv, tail -1 fill, grid_size.
// ---------------------------------------------------------------------------
__global__ void k_feat(const float* __restrict__ pts, float* __restrict__ out,
                       int N) {
    __shared__ float sf[256 * 9];
    int i = blockIdx.x * 256 + threadIdx.x;
    bool act = (i < N);
    float r[9] = {0, 0, 0, 0, 0, 0, 0, 0, 0};
    int rankv = 0;
    if (act) {
        const float2* p2 = (const float2*)(pts + (size_t)i * 6);
        float2 a = __ldg(p2);
        float2 b = __ldg(p2 + 1);
        float2 c = __ldg(p2 + 2);
        float x = a.y, y = b.x, z = b.y, inten = c.x;
        int cx = (int)((x + 50.0f) * 4.0f);
        int cy = (int)((y + 50.0f) * 4.0f);
        int key = (((int)a.x * GX + cx) * GY + cy) * NTIME + (int)c.y;
        float4 g = __ldg(&g_acc[key]);
        int2 mw = __ldg(&g_mw[key >> 5]);
        rankv = mw.y + __popc((unsigned)mw.x & ((1u << (key & 31)) - 1u));
        float inv = 1.0f / g.w;
        r[0] = x; r[1] = y; r[2] = z; r[3] = inten;
        r[4] = x - g.x * inv;
        r[5] = y - g.y * inv;
        r[6] = z - g.z * inv;
        r[7] = x - ((float)cx * 0.25f - 49.875f);
        r[8] = y - ((float)cy * 0.25f - 49.875f);
    }
    #pragma unroll
    for (int j = 0; j < 9; j++) sf[threadIdx.x * 9 + j] = r[j];
    __syncthreads();

    size_t blockBase = (size_t)blockIdx.x * (256 * 9);
    if (blockBase + 256 * 9 <= (size_t)9 * N) {
        float4* o4 = (float4*)(out + blockBase);
        const float4* s4 = (const float4*)sf;
        for (int t = threadIdx.x; t < 576; t += 256) o4[t] = s4[t];
    } else if (act) {
        for (int j = 0; j < 9; j++) out[(size_t)i * 9 + j] = r[j];
    }

    if (act) {
        out[(size_t)13 * N + i] = (float)rankv;  // unq_inv
        if (i >= g_total)
            ((float4*)(out + (size_t)9 * N))[i] = make_float4(-1.f, -1.f, -1.f, -1.f);
        if (i == 0) {
            float* gr = out + (size_t)14 * N;
            gr[0] = 400.0f; gr[1] = 400.0f; gr[2] = 1.0f;
        }
    }
}

// ---------------------------------------------------------------------------
extern "C" void kernel_launch(void* const* d_in, const int* in_sizes, int n_in,
                              void* d_out, int out_size) {
    const float* pts = (const float*)d_in[0];
    float* out = (float*)d_out;
    int N = in_sizes[0] / 6;
    int nPair = (N + 1) / 2;

    k_init<<<NKEYS / 256, 256>>>();
    k_accum<<<(nPair + 255) / 256, 256>>>(pts, N);
    k_scan1<<<NSB, GRAN>>>();
    k_rank<<<NSB, 256>>>((float4*)(out + (size_t)9 * N));
    k_feat<<<(N + 255) / 256, 256>>>(pts, out, N);
}

// round 17
// speedup vs baseline: 1.0602x; 1.0602x over previous
#include <cuda_runtime.h>
#include <stdint.h>

// ---------------------------------------------------------------------------
// PillarMotionNet voxelization, v7: R13 architecture (single-gather feat,
// rank packed into acc.w) + latency-optimized repack (thread-per-key,
// unrolled batched RMW, uniform-base key decode).
//   points: (N, 6) float32 rows [batch, x, y, z, intensity, time]
//   out   : [features (N*9) | unq (N*4) | unq_inv (N) | grid (3)] float32
// ---------------------------------------------------------------------------

#define GX 400
#define GY 400
#define NTIME 5
#define NBATCH 4
#define NKEYS (NBATCH * GX * GY * NTIME)   // 3,200,000
#define NWORDS (NKEYS / 32)                // 100,000
#define GRAN 64                            // words per rank block
#define NSB ((NWORDS + GRAN - 1) / GRAN)   // 1563

// __device__ global scratch (allocation-free rule)
__device__ float4   g_acc[NKEYS];     // {sx, sy, sz, cnt} -> .w repacked (rank<<11|cnt)
__device__ unsigned g_mask[NWORDS];   // occupancy bitmask
__device__ int      g_blockCnt[NSB];  // occupied keys per 64-word chunk
__device__ int      g_total;

// ---------------------------------------------------------------------------
// 1) Zero accumulator + bitmask + total. NKEYS = 12500 * 256 exactly.
// ---------------------------------------------------------------------------
__global__ void k_init() {
    int i = blockIdx.x * 256 + threadIdx.x;
    g_acc[i] = make_float4(0.0f, 0.0f, 0.0f, 0.0f);
    if (i < NWORDS) g_mask[i] = 0u;
    if (i == 0) g_total = 0;
}

// ---------------------------------------------------------------------------
// 2) Two points per thread: 3 x float4 loads, v4 RED + bitmask OR each.
// ---------------------------------------------------------------------------
__device__ __forceinline__ void accum_one(float b_f, float x, float y, float z,
                                          float t_f) {
    int cx = (int)((x + 50.0f) * 4.0f);
    int cy = (int)((y + 50.0f) * 4.0f);
    int key = (((int)b_f * GX + cx) * GY + cy) * NTIME + (int)t_f;
    float4* addr = &g_acc[key];
    asm volatile("red.global.add.v4.f32 [%0], {%1, %2, %3, %4};"
                 :: "l"(addr), "f"(x), "f"(y), "f"(z), "f"(1.0f) : "memory");
    atomicOr(&g_mask[key >> 5], 1u << (key & 31));
}

__global__ void k_accum(const float* __restrict__ pts, int N) {
    int t = blockIdx.x * blockDim.x + threadIdx.x;
    int i0 = t * 2;
    if (i0 >= N) return;
    if (i0 + 1 < N) {
        const float4* q = (const float4*)(pts + (size_t)i0 * 6);
        float4 A = __ldg(q);       // b0 x0 y0 z0
        float4 B = __ldg(q + 1);   // i0 t0 b1 x1
        float4 C = __ldg(q + 2);   // y1 z1 i1 t1
        accum_one(A.x, A.y, A.z, A.w, B.y);
        accum_one(B.z, B.w, C.x, C.y, C.w);
    } else {
        const float* p = pts + (size_t)i0 * 6;
        accum_one(p[0], p[1], p[2], p[3], p[5]);
    }
}

// ---------------------------------------------------------------------------
// 3a) Occupancy counts: each 256-thread block covers 256 words and emits
//     FOUR g_blockCnt entries (one per 64-word chunk) + grand total.
// ---------------------------------------------------------------------------
__global__ void k_scan1() {
    int w = blockIdx.x * 256 + threadIdx.x;
    int c = (w < NWORDS) ? __popc(g_mask[w]) : 0;
    #pragma unroll
    for (int o = 16; o > 0; o >>= 1) c += __shfl_down_sync(0xffffffffu, c, o);
    __shared__ int ws[8];
    int lane = threadIdx.x & 31, warp = threadIdx.x >> 5;
    if (lane == 0) ws[warp] = c;
    __syncthreads();
    if (threadIdx.x < 4) {
        int s = ws[2 * threadIdx.x] + ws[2 * threadIdx.x + 1];
        int cb = blockIdx.x * 4 + threadIdx.x;
        if (cb < NSB) g_blockCnt[cb] = s;
        #pragma unroll
        for (int o = 2; o > 0; o >>= 1) s += __shfl_down_sync(0xfu, s, o);
        if (threadIdx.x == 0) atomicAdd(&g_total, s);
    }
}

// ---------------------------------------------------------------------------
// 3b) Rank repack + unq emission, latency-optimized.
//     Phase 1: block exclusive offset (strided sum of g_blockCnt[0..bid)).
//     Phase 2: word offsets for 64 words (threads 0..63, two warps).
//     Phase 3: thread-per-key, 8 unrolled independent predicated RMWs ->
//              batched scattered loads; unq float4 stores coalesced.
// ---------------------------------------------------------------------------
__global__ void k_rank(float4* __restrict__ u4) {
    __shared__ int red8[8];
    __shared__ int scan2[2];
    __shared__ int s_base;
    __shared__ unsigned s_m[GRAN];
    __shared__ int s_off[GRAN];
    int tid = threadIdx.x, lane = tid & 31, warp = tid >> 5;

    // Phase 1: exclusive block offset
    int partial = 0;
    for (int j = tid; j < blockIdx.x; j += 256) partial += g_blockCnt[j];
    #pragma unroll
    for (int o = 16; o > 0; o >>= 1)
        partial += __shfl_down_sync(0xffffffffu, partial, o);
    if (lane == 0) red8[warp] = partial;
    __syncthreads();
    if (tid == 0) {
        int s = 0;
        #pragma unroll
        for (int k = 0; k < 8; k++) s += red8[k];
        s_base = s;
    }

    // Phase 2: per-word exclusive prefix over 64 words (warps 0-1)
    unsigned m = 0u;
    int c = 0;
    if (tid < GRAN) {
        int w = blockIdx.x * GRAN + tid;
        m = (w < NWORDS) ? g_mask[w] : 0u;
        c = __popc(m);
    }
    int v = c;
    #pragma unroll
    for (int o = 1; o < 32; o <<= 1) {
        int u = __shfl_up_sync(0xffffffffu, v, o);
        if (lane >= o) v += u;
    }
    if (tid < GRAN && lane == 31) scan2[warp] = v;
    __syncthreads();
    if (tid < GRAN) {
        s_m[tid] = m;
        s_off[tid] = s_base + ((warp == 1) ? scan2[0] : 0) + (v - c);
    }
    __syncthreads();

    // Phase 3: thread-per-key, unrolled; warp w handles word s*8+w at iter s
    int keyBase = blockIdx.x * (GRAN * 32);
    #pragma unroll
    for (int s = 0; s < 8; s++) {
        int local = s * 256 + tid;          // 0..2047
        int j = local >> 5;
        int ln = local & 31;
        unsigned mm = s_m[j];
        if ((mm >> ln) & 1u) {
            int rank = s_off[j] + __popc(mm & ((1u << ln) - 1u));
            int key = keyBase + local;
            float cw = g_acc[key].w;
            g_acc[key].w = __int_as_float(((unsigned)rank << 11) | (unsigned)cw);
            // decode: warp-uniform word base + lane carry propagation
            int k0 = key - ln;              // word-aligned (uniform per warp)
            int t0 = k0 % NTIME;
            int r0 = k0 / NTIME;
            int y0 = r0 % GY;
            int r1 = r0 / GY;
            int x0 = r1 % GX;
            int b0 = r1 / GX;
            int vv = t0 + ln;               // <= 35
            int q = (vv * 13) >> 6;         // == vv/5 for vv in [0,35]
            int tt = vv - 5 * q;
            int yy = y0 + q, xx = x0, bb = b0;
            if (yy >= GY) { yy -= GY; if (++xx >= GX) { xx = 0; ++bb; } }
            u4[rank] = make_float4((float)bb, (float)tt, (float)yy, (float)xx);
        }
    }
}

// ---------------------------------------------------------------------------
// 4) Per-point features: ONE packed 16B gather (R13-proven), smem-staged
//    coalesced float4 stores, unq_inv, tail -1 fill, grid_size.
// ---------------------------------------------------------------------------
__global__ void k_feat(const float* __restrict__ pts, float* __restrict__ out,
                       int N) {
    __shared__ float sf[256 * 9];
    int i = blockIdx.x * 256 + threadIdx.x;
    bool act = (i < N);
    float r[9] = {0, 0, 0, 0, 0, 0, 0, 0, 0};
    int rankv = 0;
    if (act) {
        const float2* p2 = (const float2*)(pts + (size_t)i * 6);
        float2 a = __ldg(p2);
        float2 b = __ldg(p2 + 1);
        float2 c = __ldg(p2 + 2);
        float x = a.y, y = b.x, z = b.y, inten = c.x;
        int cx = (int)((x + 50.0f) * 4.0f);
        int cy = (int)((y + 50.0f) * 4.0f);
        int key = (((int)a.x * GX + cx) * GY + cy) * NTIME + (int)c.y;
        float4 g = __ldg(&g_acc[key]);
        unsigned pk = (unsigned)__float_as_int(g.w);
        int cnt = (int)(pk & 2047u);
        rankv = (int)(pk >> 11);
        float inv = 1.0f / (float)cnt;
        r[0] = x; r[1] = y; r[2] = z; r[3] = inten;
        r[4] = x - g.x * inv;
        r[5] = y - g.y * inv;
        r[6] = z - g.z * inv;
        r[7] = x - ((float)cx * 0.25f - 49.875f);
        r[8] = y - ((float)cy * 0.25f - 49.875f);
    }
    #pragma unroll
    for (int j = 0; j < 9; j++) sf[threadIdx.x * 9 + j] = r[j];
    __syncthreads();

    size_t blockBase = (size_t)blockIdx.x * (256 * 9);
    if (blockBase + 256 * 9 <= (size_t)9 * N) {
        float4* o4 = (float4*)(out + blockBase);
        const float4* s4 = (const float4*)sf;
        for (int t = threadIdx.x; t < 576; t += 256) o4[t] = s4[t];
    } else if (act) {
        for (int j = 0; j < 9; j++) out[(size_t)i * 9 + j] = r[j];
    }

    if (act) {
        out[(size_t)13 * N + i] = (float)rankv;  // unq_inv
        if (i >= g_total)
            ((float4*)(out + (size_t)9 * N))[i] = make_float4(-1.f, -1.f, -1.f, -1.f);
        if (i == 0) {
            float* gr = out + (size_t)14 * N;
            gr[0] = 400.0f; gr[1] = 400.0f; gr[2] = 1.0f;
        }
    }
}

// ---------------------------------------------------------------------------
extern "C" void kernel_launch(void* const* d_in, const int* in_sizes, int n_in,
                              void* d_out, int out_size) {
    const float* pts = (const float*)d_in[0];
    float* out = (float*)d_out;
    int N = in_sizes[0] / 6;
    int nPair = (N + 1) / 2;

    k_init<<<NKEYS / 256, 256>>>();
    k_accum<<<(nPair + 255) / 256, 256>>>(pts, N);
    k_scan1<<<(NWORDS + 255) / 256, 256>>>();
    k_rank<<<NSB, 256>>>((float4*)(out + (size_t)9 * N));
    k_feat<<<(N + 255) / 256, 256>>>(pts, out, N);
}